// round 14
// baseline (speedup 1.0000x reference)
#include <cuda_runtime.h>

typedef unsigned long long ull;

static constexpr int T  = 256;
static constexpr int F  = 16;
static constexpr int U1 = 24;
static constexpr int U2 = 48;
#define LN_EPS 1e-3f

// ---------------- packed f32x2 helpers ----------------
__device__ __forceinline__ ull pk2(float lo, float hi) {
    ull r; asm("mov.b64 %0, {%1, %2};" : "=l"(r) : "f"(lo), "f"(hi)); return r;
}
__device__ __forceinline__ ull dup2(float v) { return pk2(v, v); }
__device__ __forceinline__ float2 un2(ull p) {
    float2 r; asm("mov.b64 {%0, %1}, %2;" : "=f"(r.x), "=f"(r.y) : "l"(p)); return r;
}
__device__ __forceinline__ ull ffma2(ull a, ull b, ull c) {
    ull d; asm("fma.rn.f32x2 %0, %1, %2, %3;" : "=l"(d) : "l"(a), "l"(b), "l"(c)); return d;
}
__device__ __forceinline__ ull fadd2(ull a, ull b) {
    ull d; asm("add.rn.f32x2 %0, %1, %2;" : "=l"(d) : "l"(a), "l"(b)); return d;
}
__device__ __forceinline__ ull fmul2(ull a, ull b) {
    ull d; asm("mul.rn.f32x2 %0, %1, %2;" : "=l"(d) : "l"(a), "l"(b)); return d;
}

// branch-free accurate tanh: 1 - 2/(1+e^{2x})
__device__ __forceinline__ float tanh_f(float x) {
    float e = __expf(2.0f * x);
    return 1.0f - __fdividef(2.0f, 1.0f + e);
}

__device__ __forceinline__ ull mkp(float lo, float hi) {
    return ((ull)__float_as_uint(hi) << 32) | __float_as_uint(lo);
}

// one-sided pair barrier: producer warp arrives (32), consumer warp syncs (32) => 64
__device__ __forceinline__ void barw_arrive(int id) {
    asm volatile("bar.arrive %0, 64;" :: "r"(id) : "memory");
}
__device__ __forceinline__ void barw_sync(int id) {
    asm volatile("bar.sync %0, 64;" :: "r"(id) : "memory");
}
// full trio barrier: all 3 warps of a trio call (96 arrivals, canonical)
__device__ __forceinline__ void bart_full(int id) {
    asm volatile("bar.sync %0, 96;" :: "r"(id) : "memory");
}

// ---------------- fused weight bundle (identical to validated R8/R11) ----------------
struct __align__(16) CW2 {
    ull W1rm[4][8][6];    // W1@Wr1, [w][kp][j]
    ull Wr1m[4][12][6];
    ull Mm  [4][12][12];  // (g1.*W2)@Wr2
    ull Wr2m[4][24][12];
    ull B1r [4][3];
    ull B2n [4][6];
    ull Cmp [4][6];
    ull G2f [24];
    ull Be2f[24];
    ull Wof [24];
    float bout;
    float pad[3];
};
__device__ CW2 d_stage;

// ---------------- prep kernel (verbatim from validated R8/R11) ----------------
__global__ void prep_kernel(const float* __restrict__ W1,  const float* __restrict__ b1,
                            const float* __restrict__ Wr1, const float* __restrict__ br1,
                            const float* __restrict__ g1,  const float* __restrict__ be1,
                            const float* __restrict__ W2,  const float* __restrict__ b2,
                            const float* __restrict__ Wr2, const float* __restrict__ br2,
                            const float* __restrict__ g2,  const float* __restrict__ be2,
                            const float* __restrict__ Wout, const float* __restrict__ bout)
{
    const int tid = threadIdx.x;  // 256 threads
    for (int idx = tid; idx < 4 * 8 * 6; idx += 256) {
        int w = idx / 48, kp = (idx / 6) % 8, j = idx % 6;
        int k = 2 * kp + j / 3, u = 6 * w + 2 * (j % 3);
        float lo = 0.f, hi = 0.f;
        for (int v = 0; v < U1; ++v) {
            float a = W1[k * U1 + v];
            lo += a * Wr1[v * U1 + u];
            hi += a * Wr1[v * U1 + u + 1];
        }
        d_stage.W1rm[w][kp][j] = mkp(lo, hi);
    }
    for (int idx = tid; idx < 4 * 12 * 6; idx += 256) {
        int w = idx / 72, p = (idx / 6) % 12, j = idx % 6;
        int k = 2 * p + j / 3, u = 6 * w + 2 * (j % 3);
        d_stage.Wr1m[w][p][j] = mkp(Wr1[k * U1 + u], Wr1[k * U1 + u + 1]);
    }
    for (int idx = tid; idx < 4 * 12 * 12; idx += 256) {
        int w = idx / 144, p = (idx / 12) % 12, j = idx % 12;
        int k = 2 * p + j / 6, u = 12 * w + 2 * (j % 6);
        float lo = 0.f, hi = 0.f;
        for (int v = 0; v < U2; ++v) {
            float a = g1[k] * W2[k * U2 + v];
            lo += a * Wr2[v * U2 + u];
            hi += a * Wr2[v * U2 + u + 1];
        }
        d_stage.Mm[w][p][j] = mkp(lo, hi);
    }
    for (int idx = tid; idx < 4 * 24 * 12; idx += 256) {
        int w = idx / 288, p = (idx % 288) / 12, j = idx % 12;
        int k = 2 * p + j / 6, u = 12 * w + 2 * (j % 6);
        d_stage.Wr2m[w][p][j] = mkp(Wr2[k * U2 + u], Wr2[k * U2 + u + 1]);
    }
    for (int idx = tid; idx < 12; idx += 256) {
        int w = idx / 3, j = idx % 3, u = 6 * w + 2 * j;
        float lo = br1[u], hi = br1[u + 1];
        for (int k = 0; k < U1; ++k) {
            lo += b1[k] * Wr1[k * U1 + u];
            hi += b1[k] * Wr1[k * U1 + u + 1];
        }
        d_stage.B1r[w][j] = mkp(lo, hi);
    }
    for (int idx = tid; idx < 24; idx += 256) {
        int w = idx / 6, j = idx % 6, u = 12 * w + 2 * j;
        float blo = br2[u], bhi = br2[u + 1];
        float clo = 0.f, chi = 0.f;
        for (int v = 0; v < U2; ++v) {
            float bf = b2[v], cv = 0.f;
            for (int k = 0; k < U1; ++k) {
                bf += be1[k] * W2[k * U2 + v];
                cv += g1[k] * W2[k * U2 + v];
            }
            blo += bf * Wr2[v * U2 + u];
            bhi += bf * Wr2[v * U2 + u + 1];
            clo += cv * Wr2[v * U2 + u];
            chi += cv * Wr2[v * U2 + u + 1];
        }
        d_stage.B2n[w][j] = mkp(blo, bhi);
        d_stage.Cmp[w][j] = mkp(clo, chi);
    }
    for (int idx = tid; idx < 24; idx += 256) {
        int u = 2 * idx;
        d_stage.G2f[idx]  = mkp(g2[u],   g2[u + 1]);
        d_stage.Be2f[idx] = mkp(be2[u],  be2[u + 1]);
        d_stage.Wof[idx]  = mkp(Wout[u], Wout[u + 1]);
    }
    if (tid == 0) d_stage.bout = bout[0];
}

// ---------------- smem layout ----------------
struct __align__(16) Smem4 {
    CW2 cw;
    ull sn[2][12][64];        // ns1 pairs [buf][pair][row]
    ull sy[2][24][64];        // ns2 pairs
    ull pa[4][2][3][64];      // phase1 partials from kt0 (slot0) and kt1 (slot1)
    ull pbe[4][3][6][64];     // e-partials: [w][src kt][unit-pair j][row]
    float sinb[2][16][66];    // staged input
};

// ---------------- main scan kernel ----------------
// 384 threads = 12 warps = 4 trios. Trio (w, kt): slice w, k-third kt.
// lane r -> rows 2r, 2r+1. 64 rows/CTA, grid 128.
__global__ __launch_bounds__(384, 1)
void rnn_main(const float* __restrict__ seq, float* __restrict__ out)
{
    extern __shared__ __align__(16) char smem_raw[];
    Smem4* S = reinterpret_cast<Smem4*>(smem_raw);

    const int tid  = threadIdx.x;
    const int warp = tid >> 5;
    const int lane = tid & 31;
    const int w    = warp & 3;
    const int kt   = warp >> 2;       // 0,1,2
    const int r0   = 2 * lane;
    const int rowbase = blockIdx.x * 64;
    const int idA  = 1 + w;           // kt0 arrives, kt2 syncs
    const int idB  = 5 + w;           // kt1 arrives, kt2 syncs
    const int idT  = 9 + w;           // full trio barrier

    // cooperative weight copy
    {
        const ull* gsrc = reinterpret_cast<const ull*>(&d_stage);
        ull* sdst = reinterpret_cast<ull*>(&S->cw);
        const int N = (int)(sizeof(CW2) / 8);
        for (int i = tid; i < N; i += 384) sdst[i] = gsrc[i];
    }

    // prologue: stage t=0,1 inputs; zero state buffers sn[1], sy[1]
    {
        // 2 buffers x 64 rows x 4 float4-chunks = 512 float4
        for (int idx = tid; idx < 512; idx += 384) {
            int buf = idx >> 8, rem = idx & 255;
            int prow = rem >> 2, pch = rem & 3;
            const float4* gq = reinterpret_cast<const float4*>(
                                   seq + (size_t)(rowbase + prow) * (T * F)) + buf * 4 + pch;
            float4 v = *gq;
            S->sinb[buf][4 * pch + 0][prow] = v.x;
            S->sinb[buf][4 * pch + 1][prow] = v.y;
            S->sinb[buf][4 * pch + 2][prow] = v.z;
            S->sinb[buf][4 * pch + 3][prow] = v.w;
        }
        ull* z1 = &S->sn[1][0][0];
        for (int i = tid; i < 12 * 64; i += 384) z1[i] = 0ull;
        ull* z2 = &S->sy[1][0][0];
        for (int i = tid; i < 24 * 64; i += 384) z2[i] = 0ull;
    }
    __syncthreads();

    // per-step input staging (kt0 warps = tids 0..127): 8 floats each
    const int srow = (tid & 127) >> 1, half = tid & 1;
    const float4* gp0 = reinterpret_cast<const float4*>(
                            seq + (size_t)(rowbase + srow) * (T * F)) + half * 2;

    for (int t = 0; t < T; ++t) {
        const int cur = t & 1, oth = cur ^ 1;
        const int tn2 = (t + 2 < T) ? (t + 2) : (T - 1);
        float4 nv0, nv1;
        if (kt == 0) { nv0 = gp0[tn2 * 4]; nv1 = gp0[tn2 * 4 + 1]; }

        // e accumulators: 6 unit-pairs x 2 rows
        ull e0[6], e1[6];
        #pragma unroll
        for (int j = 0; j < 6; ++j) {
            ull bb = (kt == 0) ? S->cw.B2n[w][j] : 0ull;
            e0[j] = bb; e1[j] = bb;
        }

        // ================= Phase 1 (3-way k-split layer 1) =====================
        if (kt == 0) {
            ull a0[3], a1[3];
            #pragma unroll
            for (int j = 0; j < 3; ++j) { a0[j] = S->cw.B1r[w][j]; a1[j] = a0[j]; }
            #pragma unroll
            for (int kp = 0; kp < 8; ++kp) {
                const ulonglong2* q = reinterpret_cast<const ulonglong2*>(S->cw.W1rm[w][kp]);
                ulonglong2 q0 = q[0], q1 = q[1], q2 = q[2];
                float2 f0 = *reinterpret_cast<const float2*>(&S->sinb[cur][2 * kp][r0]);
                float2 f1 = *reinterpret_cast<const float2*>(&S->sinb[cur][2 * kp + 1][r0]);
                ull k00 = dup2(f0.x), k01 = dup2(f0.y);
                ull k10 = dup2(f1.x), k11 = dup2(f1.y);
                a0[0] = ffma2(k00, q0.x, a0[0]); a0[1] = ffma2(k00, q0.y, a0[1]); a0[2] = ffma2(k00, q1.x, a0[2]);
                a0[0] = ffma2(k10, q1.y, a0[0]); a0[1] = ffma2(k10, q2.x, a0[1]); a0[2] = ffma2(k10, q2.y, a0[2]);
                a1[0] = ffma2(k01, q0.x, a1[0]); a1[1] = ffma2(k01, q0.y, a1[1]); a1[2] = ffma2(k01, q1.x, a1[2]);
                a1[0] = ffma2(k11, q1.y, a1[0]); a1[1] = ffma2(k11, q2.x, a1[1]); a1[2] = ffma2(k11, q2.y, a1[2]);
            }
            #pragma unroll
            for (int j = 0; j < 3; ++j)
                *reinterpret_cast<ulonglong2*>(&S->pa[w][0][j][r0]) = make_ulonglong2(a0[j], a1[j]);
            barw_arrive(idA);
        } else if (kt == 1) {
            ull a0[3] = {0,0,0}, a1[3] = {0,0,0};
            #pragma unroll
            for (int pp = 0; pp < 6; ++pp) {
                const ulonglong2* q = reinterpret_cast<const ulonglong2*>(S->cw.Wr1m[w][pp]);
                ulonglong2 q0 = q[0], q1 = q[1], q2 = q[2];
                ulonglong2 X = *reinterpret_cast<const ulonglong2*>(&S->sn[oth][pp][r0]);
                float2 u0 = un2(X.x), u1 = un2(X.y);
                ull k0 = dup2(u0.x), k1 = dup2(u0.y);
                a0[0] = ffma2(k0, q0.x, a0[0]); a0[1] = ffma2(k0, q0.y, a0[1]); a0[2] = ffma2(k0, q1.x, a0[2]);
                a0[0] = ffma2(k1, q1.y, a0[0]); a0[1] = ffma2(k1, q2.x, a0[1]); a0[2] = ffma2(k1, q2.y, a0[2]);
                ull m0 = dup2(u1.x), m1 = dup2(u1.y);
                a1[0] = ffma2(m0, q0.x, a1[0]); a1[1] = ffma2(m0, q0.y, a1[1]); a1[2] = ffma2(m0, q1.x, a1[2]);
                a1[0] = ffma2(m1, q1.y, a1[0]); a1[1] = ffma2(m1, q2.x, a1[1]); a1[2] = ffma2(m1, q2.y, a1[2]);
            }
            #pragma unroll
            for (int j = 0; j < 3; ++j)
                *reinterpret_cast<ulonglong2*>(&S->pa[w][1][j][r0]) = make_ulonglong2(a0[j], a1[j]);
            barw_arrive(idB);
        } else {
            ull a0[3] = {0,0,0}, a1[3] = {0,0,0};
            #pragma unroll
            for (int pp = 6; pp < 12; ++pp) {
                const ulonglong2* q = reinterpret_cast<const ulonglong2*>(S->cw.Wr1m[w][pp]);
                ulonglong2 q0 = q[0], q1 = q[1], q2 = q[2];
                ulonglong2 X = *reinterpret_cast<const ulonglong2*>(&S->sn[oth][pp][r0]);
                float2 u0 = un2(X.x), u1 = un2(X.y);
                ull k0 = dup2(u0.x), k1 = dup2(u0.y);
                a0[0] = ffma2(k0, q0.x, a0[0]); a0[1] = ffma2(k0, q0.y, a0[1]); a0[2] = ffma2(k0, q1.x, a0[2]);
                a0[0] = ffma2(k1, q1.y, a0[0]); a0[1] = ffma2(k1, q2.x, a0[1]); a0[2] = ffma2(k1, q2.y, a0[2]);
                ull m0 = dup2(u1.x), m1 = dup2(u1.y);
                a1[0] = ffma2(m0, q0.x, a1[0]); a1[1] = ffma2(m0, q0.y, a1[1]); a1[2] = ffma2(m0, q1.x, a1[2]);
                a1[0] = ffma2(m1, q1.y, a1[0]); a1[1] = ffma2(m1, q2.x, a1[1]); a1[2] = ffma2(m1, q2.y, a1[2]);
            }
            barw_sync(idA);
            barw_sync(idB);
            #pragma unroll
            for (int j = 0; j < 3; ++j) {
                ulonglong2 P0 = *reinterpret_cast<const ulonglong2*>(&S->pa[w][0][j][r0]);
                ulonglong2 P1 = *reinterpret_cast<const ulonglong2*>(&S->pa[w][1][j][r0]);
                a0[j] = fadd2(fadd2(a0[j], P0.x), P1.x);
                a1[j] = fadd2(fadd2(a1[j], P0.y), P1.y);
            }
            #pragma unroll
            for (int j = 0; j < 3; ++j) {
                float2 u0 = un2(a0[j]), u1 = un2(a1[j]);
                *reinterpret_cast<ulonglong2*>(&S->sn[cur][3 * w + j][r0]) =
                    make_ulonglong2(pk2(tanh_f(u0.x), tanh_f(u0.y)),
                                    pk2(tanh_f(u1.x), tanh_f(u1.y)));
            }
        }

        // ================= Phase 2a: e k-third  (8 pp each) ====================
        {
            const int ppb = 8 * kt;
            #pragma unroll
            for (int i = 0; i < 8; ++i) {
                const int pp = ppb + i;
                const ulonglong2* q = reinterpret_cast<const ulonglong2*>(S->cw.Wr2m[w][pp]);
                ulonglong2 q0 = q[0], q1 = q[1], q2 = q[2];
                ulonglong2 q3 = q[3], q4 = q[4], q5 = q[5];
                ulonglong2 Y = *reinterpret_cast<const ulonglong2*>(&S->sy[oth][pp][r0]);
                float2 u0 = un2(Y.x), u1 = un2(Y.y);
                ull k0 = dup2(u0.x), k1 = dup2(u0.y);
                e0[0] = ffma2(k0, q0.x, e0[0]); e0[1] = ffma2(k0, q0.y, e0[1]); e0[2] = ffma2(k0, q1.x, e0[2]);
                e0[3] = ffma2(k0, q1.y, e0[3]); e0[4] = ffma2(k0, q2.x, e0[4]); e0[5] = ffma2(k0, q2.y, e0[5]);
                e0[0] = ffma2(k1, q3.x, e0[0]); e0[1] = ffma2(k1, q3.y, e0[1]); e0[2] = ffma2(k1, q4.x, e0[2]);
                e0[3] = ffma2(k1, q4.y, e0[3]); e0[4] = ffma2(k1, q5.x, e0[4]); e0[5] = ffma2(k1, q5.y, e0[5]);
                ull m0 = dup2(u1.x), m1 = dup2(u1.y);
                e1[0] = ffma2(m0, q0.x, e1[0]); e1[1] = ffma2(m0, q0.y, e1[1]); e1[2] = ffma2(m0, q1.x, e1[2]);
                e1[3] = ffma2(m0, q1.y, e1[3]); e1[4] = ffma2(m0, q2.x, e1[4]); e1[5] = ffma2(m0, q2.y, e1[5]);
                e1[0] = ffma2(m1, q3.x, e1[0]); e1[1] = ffma2(m1, q3.y, e1[1]); e1[2] = ffma2(m1, q4.x, e1[2]);
                e1[3] = ffma2(m1, q4.y, e1[3]); e1[4] = ffma2(m1, q5.x, e1[4]); e1[5] = ffma2(m1, q5.y, e1[5]);
            }
        }

        __syncthreads();   // sync1: sn[cur] visible; sinb[cur] reads done

        // stage input t+2 (kt0 warps)
        if (kt == 0) {
            S->sinb[cur][8 * half + 0][srow] = nv0.x;
            S->sinb[cur][8 * half + 1][srow] = nv0.y;
            S->sinb[cur][8 * half + 2][srow] = nv0.z;
            S->sinb[cur][8 * half + 3][srow] = nv0.w;
            S->sinb[cur][8 * half + 4][srow] = nv1.x;
            S->sinb[cur][8 * half + 5][srow] = nv1.y;
            S->sinb[cur][8 * half + 6][srow] = nv1.z;
            S->sinb[cur][8 * half + 7][srow] = nv1.w;
        }

        // ================= Phase 2b: Mm j-split + stats + e exchange ===========
        ull cA0 = 0, cA1 = 0, cB0 = 0, cB1 = 0;   // own unit-pairs 2kt (A), 2kt+1 (B), rows 0/1
        ull sm0 = 0, sm1 = 0, sq0 = 0, sq1 = 0;
        #pragma unroll
        for (int pp = 0; pp < 12; ++pp) {
            ulonglong2 X = *reinterpret_cast<const ulonglong2*>(&S->sn[cur][pp][r0]);
            sm0 = fadd2(sm0, X.x); sq0 = ffma2(X.x, X.x, sq0);
            sm1 = fadd2(sm1, X.y); sq1 = ffma2(X.y, X.y, sq1);
            ulonglong2 q0 = *reinterpret_cast<const ulonglong2*>(&S->cw.Mm[w][pp][2 * kt]);
            ulonglong2 q1 = *reinterpret_cast<const ulonglong2*>(&S->cw.Mm[w][pp][6 + 2 * kt]);
            float2 u0 = un2(X.x), u1 = un2(X.y);
            ull k0 = dup2(u0.x), k1 = dup2(u0.y);
            cA0 = ffma2(k0, q0.x, cA0); cB0 = ffma2(k0, q0.y, cB0);
            cA0 = ffma2(k1, q1.x, cA0); cB0 = ffma2(k1, q1.y, cB0);
            ull m0 = dup2(u1.x), m1 = dup2(u1.y);
            cA1 = ffma2(m0, q0.x, cA1); cB1 = ffma2(m0, q0.y, cB1);
            cA1 = ffma2(m1, q1.x, cA1); cB1 = ffma2(m1, q1.y, cB1);
        }
        // ship e-partials for the 4 foreign unit-pairs
        #pragma unroll
        for (int j = 0; j < 6; ++j) {
            if ((j >> 1) != kt) {
                *reinterpret_cast<ulonglong2*>(&S->pbe[w][kt][j][r0]) =
                    make_ulonglong2(e0[j], e1[j]);
            }
        }
        bart_full(idT);
        // gather partners' e for own unit-pairs
        {
            const int ka = (kt + 1) % 3, kb = (kt + 2) % 3;
            const int jA = 2 * kt, jB = 2 * kt + 1;
            ulonglong2 P, Q;
            P = *reinterpret_cast<const ulonglong2*>(&S->pbe[w][ka][jA][r0]);
            Q = *reinterpret_cast<const ulonglong2*>(&S->pbe[w][kb][jA][r0]);
            e0[jA] = fadd2(fadd2(e0[jA], P.x), Q.x);
            e1[jA] = fadd2(fadd2(e1[jA], P.y), Q.y);
            P = *reinterpret_cast<const ulonglong2*>(&S->pbe[w][ka][jB][r0]);
            Q = *reinterpret_cast<const ulonglong2*>(&S->pbe[w][kb][jB][r0]);
            e0[jB] = fadd2(fadd2(e0[jB], P.x), Q.x);
            e1[jB] = fadd2(fadd2(e1[jB], P.y), Q.y);
            // LN + finalize own 2 unit-pairs
            float2 us = un2(sm0), uq = un2(sq0);
            float mu   = (us.x + us.y) * (1.0f / 24.0f);
            float var  = fmaf(-mu, mu, (uq.x + uq.y) * (1.0f / 24.0f));
            float rstd = rsqrtf(var + LN_EPS);
            ull mun = dup2(-mu), rsd = dup2(rstd);
            cA0 = ffma2(rsd, ffma2(mun, S->cw.Cmp[w][jA], cA0), e0[jA]);
            cB0 = ffma2(rsd, ffma2(mun, S->cw.Cmp[w][jB], cB0), e0[jB]);
            float2 vs = un2(sm1), vq = un2(sq1);
            float mu1   = (vs.x + vs.y) * (1.0f / 24.0f);
            float var1  = fmaf(-mu1, mu1, (vq.x + vq.y) * (1.0f / 24.0f));
            float rstd1 = rsqrtf(var1 + LN_EPS);
            ull mun1 = dup2(-mu1), rsd1 = dup2(rstd1);
            cA1 = ffma2(rsd1, ffma2(mun1, S->cw.Cmp[w][jA], cA1), e1[jA]);
            cB1 = ffma2(rsd1, ffma2(mun1, S->cw.Cmp[w][jB], cB1), e1[jB]);
            float2 u0, u1;
            u0 = un2(cA0); u1 = un2(cA1);
            *reinterpret_cast<ulonglong2*>(&S->sy[cur][6 * w + jA][r0]) =
                make_ulonglong2(pk2(tanh_f(u0.x), tanh_f(u0.y)),
                                pk2(tanh_f(u1.x), tanh_f(u1.y)));
            u0 = un2(cB0); u1 = un2(cB1);
            *reinterpret_cast<ulonglong2*>(&S->sy[cur][6 * w + jB][r0]) =
                make_ulonglong2(pk2(tanh_f(u0.x), tanh_f(u0.y)),
                                pk2(tanh_f(u1.x), tanh_f(u1.y)));
        }
        __syncthreads();   // sync2: sy[cur] + staged input visible; pa/pbe WARs cleared
    }

    // ---- epilogue: sigmoid(LN(ns2; g2,be2) @ Wout + bout) by warp 0 ----
    if (warp == 0) {
        ull zp0[24], zp1[24];
        #pragma unroll
        for (int pp = 0; pp < 24; ++pp) {
            ulonglong2 X = *reinterpret_cast<const ulonglong2*>(&S->sy[1][pp][r0]);
            zp0[pp] = X.x; zp1[pp] = X.y;
        }
        float res[2];
        #pragma unroll
        for (int rr = 0; rr < 2; ++rr) {
            const ull* zp = rr ? zp1 : zp0;
            ull sm2 = zp[0], sq2 = fmul2(zp[0], zp[0]);
            #pragma unroll
            for (int pp = 1; pp < 24; ++pp) {
                sm2 = fadd2(sm2, zp[pp]);
                sq2 = ffma2(zp[pp], zp[pp], sq2);
            }
            float2 us = un2(sm2), uq = un2(sq2);
            float mu   = (us.x + us.y) * (1.0f / 48.0f);
            float var  = fmaf(-mu, mu, (uq.x + uq.y) * (1.0f / 48.0f));
            float rstd = rsqrtf(var + LN_EPS);
            ull mun = dup2(-mu), rsd = dup2(rstd);
            ull acc = 0;
            #pragma unroll
            for (int pp = 0; pp < 24; ++pp) {
                ull h = fmul2(fadd2(zp[pp], mun), rsd);
                h = ffma2(h, S->cw.G2f[pp], S->cw.Be2f[pp]);
                acc = ffma2(h, S->cw.Wof[pp], acc);
            }
            float2 ua = un2(acc);
            float z = ua.x + ua.y + S->cw.bout;
            res[rr] = __fdividef(1.0f, 1.0f + __expf(-z));
        }
        *reinterpret_cast<float2*>(&out[rowbase + r0]) = make_float2(res[0], res[1]);
    }
}

extern "C" void kernel_launch(void* const* d_in, const int* in_sizes, int n_in,
                              void* d_out, int out_size)
{
    const float* seq  = (const float*)d_in[0];
    const float* W1   = (const float*)d_in[1];
    const float* b1   = (const float*)d_in[2];
    const float* Wr1  = (const float*)d_in[3];
    const float* br1  = (const float*)d_in[4];
    const float* g1   = (const float*)d_in[5];
    const float* be1  = (const float*)d_in[6];
    const float* W2   = (const float*)d_in[7];
    const float* b2   = (const float*)d_in[8];
    const float* Wr2  = (const float*)d_in[9];
    const float* br2  = (const float*)d_in[10];
    const float* g2   = (const float*)d_in[11];
    const float* be2  = (const float*)d_in[12];
    const float* Wout = (const float*)d_in[13];
    const float* bout = (const float*)d_in[14];

    prep_kernel<<<1, 256>>>(W1, b1, Wr1, br1, g1, be1,
                            W2, b2, Wr2, br2, g2, be2, Wout, bout);

    static int smem_configured = 0;
    if (!smem_configured) {
        cudaFuncSetAttribute(rnn_main, cudaFuncAttributeMaxDynamicSharedMemorySize,
                             (int)sizeof(Smem4));
        smem_configured = 1;
    }

    const int B = in_sizes[0] / (T * F);     // 8192
    rnn_main<<<B / 64, 384, sizeof(Smem4)>>>(seq, (float*)d_out);
}

// round 17
// speedup vs baseline: 1.4209x; 1.4209x over previous
#include <cuda_runtime.h>

typedef unsigned long long ull;

static constexpr int T  = 256;
static constexpr int F  = 16;
static constexpr int U1 = 24;
static constexpr int U2 = 48;
#define LN_EPS 1e-3f

// ---------------- packed f32x2 helpers ----------------
__device__ __forceinline__ ull pk2(float lo, float hi) {
    ull r; asm("mov.b64 %0, {%1, %2};" : "=l"(r) : "f"(lo), "f"(hi)); return r;
}
__device__ __forceinline__ ull dup2(float v) { return pk2(v, v); }
__device__ __forceinline__ float2 un2(ull p) {
    float2 r; asm("mov.b64 {%0, %1}, %2;" : "=f"(r.x), "=f"(r.y) : "l"(p)); return r;
}
__device__ __forceinline__ ull ffma2(ull a, ull b, ull c) {
    ull d; asm("fma.rn.f32x2 %0, %1, %2, %3;" : "=l"(d) : "l"(a), "l"(b), "l"(c)); return d;
}
__device__ __forceinline__ ull fadd2(ull a, ull b) {
    ull d; asm("add.rn.f32x2 %0, %1, %2;" : "=l"(d) : "l"(a), "l"(b)); return d;
}
__device__ __forceinline__ ull fmul2(ull a, ull b) {
    ull d; asm("mul.rn.f32x2 %0, %1, %2;" : "=l"(d) : "l"(a), "l"(b)); return d;
}

// branch-free accurate tanh: 1 - 2/(1+e^{2x})
__device__ __forceinline__ float tanh_f(float x) {
    float e = __expf(2.0f * x);
    return 1.0f - __fdividef(2.0f, 1.0f + e);
}

__device__ __forceinline__ ull mkp(float lo, float hi) {
    return ((ull)__float_as_uint(hi) << 32) | __float_as_uint(lo);
}

// one-sided pair barrier: producer warp arrives (32), consumer warp syncs (32) => 64
__device__ __forceinline__ void barw_arrive(int id) {
    asm volatile("bar.arrive %0, 64;" :: "r"(id) : "memory");
}
__device__ __forceinline__ void barw_sync(int id) {
    asm volatile("bar.sync %0, 64;" :: "r"(id) : "memory");
}
// group barrier: all 4 warps of one kh-group (128 threads, canonical)
__device__ __forceinline__ void barg_sync(int id) {
    asm volatile("bar.sync %0, 128;" :: "r"(id) : "memory");
}

// ---------------- fused weight bundle (identical to validated R8/R11) ----------------
struct __align__(16) CW2 {
    ull W1rm[4][8][6];    // W1@Wr1, [w][kp][j]
    ull Wr1m[4][12][6];
    ull Mm  [4][12][12];  // (g1.*W2)@Wr2
    ull Wr2m[4][24][12];
    ull B1r [4][3];
    ull B2n [4][6];
    ull Cmp [4][6];
    ull G2f [24];
    ull Be2f[24];
    ull Wof [24];
    float bout;
    float pad[3];
};
__device__ CW2 d_stage;

// ---------------- prep kernel (verbatim from validated R8/R11) ----------------
__global__ void prep_kernel(const float* __restrict__ W1,  const float* __restrict__ b1,
                            const float* __restrict__ Wr1, const float* __restrict__ br1,
                            const float* __restrict__ g1,  const float* __restrict__ be1,
                            const float* __restrict__ W2,  const float* __restrict__ b2,
                            const float* __restrict__ Wr2, const float* __restrict__ br2,
                            const float* __restrict__ g2,  const float* __restrict__ be2,
                            const float* __restrict__ Wout, const float* __restrict__ bout)
{
    const int tid = threadIdx.x;  // 256 threads
    for (int idx = tid; idx < 4 * 8 * 6; idx += 256) {
        int w = idx / 48, kp = (idx / 6) % 8, j = idx % 6;
        int k = 2 * kp + j / 3, u = 6 * w + 2 * (j % 3);
        float lo = 0.f, hi = 0.f;
        for (int v = 0; v < U1; ++v) {
            float a = W1[k * U1 + v];
            lo += a * Wr1[v * U1 + u];
            hi += a * Wr1[v * U1 + u + 1];
        }
        d_stage.W1rm[w][kp][j] = mkp(lo, hi);
    }
    for (int idx = tid; idx < 4 * 12 * 6; idx += 256) {
        int w = idx / 72, p = (idx / 6) % 12, j = idx % 6;
        int k = 2 * p + j / 3, u = 6 * w + 2 * (j % 3);
        d_stage.Wr1m[w][p][j] = mkp(Wr1[k * U1 + u], Wr1[k * U1 + u + 1]);
    }
    for (int idx = tid; idx < 4 * 12 * 12; idx += 256) {
        int w = idx / 144, p = (idx / 12) % 12, j = idx % 12;
        int k = 2 * p + j / 6, u = 12 * w + 2 * (j % 6);
        float lo = 0.f, hi = 0.f;
        for (int v = 0; v < U2; ++v) {
            float a = g1[k] * W2[k * U2 + v];
            lo += a * Wr2[v * U2 + u];
            hi += a * Wr2[v * U2 + u + 1];
        }
        d_stage.Mm[w][p][j] = mkp(lo, hi);
    }
    for (int idx = tid; idx < 4 * 24 * 12; idx += 256) {
        int w = idx / 288, p = (idx % 288) / 12, j = idx % 12;
        int k = 2 * p + j / 6, u = 12 * w + 2 * (j % 6);
        d_stage.Wr2m[w][p][j] = mkp(Wr2[k * U2 + u], Wr2[k * U2 + u + 1]);
    }
    for (int idx = tid; idx < 12; idx += 256) {
        int w = idx / 3, j = idx % 3, u = 6 * w + 2 * j;
        float lo = br1[u], hi = br1[u + 1];
        for (int k = 0; k < U1; ++k) {
            lo += b1[k] * Wr1[k * U1 + u];
            hi += b1[k] * Wr1[k * U1 + u + 1];
        }
        d_stage.B1r[w][j] = mkp(lo, hi);
    }
    for (int idx = tid; idx < 24; idx += 256) {
        int w = idx / 6, j = idx % 6, u = 12 * w + 2 * j;
        float blo = br2[u], bhi = br2[u + 1];
        float clo = 0.f, chi = 0.f;
        for (int v = 0; v < U2; ++v) {
            float bf = b2[v], cv = 0.f;
            for (int k = 0; k < U1; ++k) {
                bf += be1[k] * W2[k * U2 + v];
                cv += g1[k] * W2[k * U2 + v];
            }
            blo += bf * Wr2[v * U2 + u];
            bhi += bf * Wr2[v * U2 + u + 1];
            clo += cv * Wr2[v * U2 + u];
            chi += cv * Wr2[v * U2 + u + 1];
        }
        d_stage.B2n[w][j] = mkp(blo, bhi);
        d_stage.Cmp[w][j] = mkp(clo, chi);
    }
    for (int idx = tid; idx < 24; idx += 256) {
        int u = 2 * idx;
        d_stage.G2f[idx]  = mkp(g2[u],   g2[u + 1]);
        d_stage.Be2f[idx] = mkp(be2[u],  be2[u + 1]);
        d_stage.Wof[idx]  = mkp(Wout[u], Wout[u + 1]);
    }
    if (tid == 0) d_stage.bout = bout[0];
}

// ---------------- smem layout ----------------
struct __align__(16) Smem5 {
    CW2 cw;
    ull sn[2][12][64];        // ns1 pairs [buf][pair][row]
    ull sy[2][24][64];        // ns2 pairs
    ull pb1[4][3][64];        // phase1 x-partials (A -> B)
    ull pbe[4][6][64];        // e-partials (A -> B)
    float sinb[2][16][66];    // staged input
};

// ---------------- main scan kernel ----------------
// 256 threads = 8 warps = 4 pairs. Pair (w, w+4): slice w; kh=0 ("A") / kh=1 ("B").
// One-directional ships (A->B only); group-local mid-step barriers; 1 CTA sync/step.
__global__ __launch_bounds__(256, 1)
void rnn_main(const float* __restrict__ seq, float* __restrict__ out)
{
    extern __shared__ __align__(16) char smem_raw[];
    Smem5* S = reinterpret_cast<Smem5*>(smem_raw);

    const int tid  = threadIdx.x;
    const int warp = tid >> 5;
    const int lane = tid & 31;
    const int w    = warp & 3;
    const int kh   = warp >> 2;       // 0 = A, 1 = B
    const int r0   = 2 * lane;
    const int rowbase = blockIdx.x * 64;
    const int pidA = 1 + w;           // A arrives (x-partial), B syncs
    const int pidE = 5 + w;           // A arrives (e-partial), B syncs
    // group barriers: id 9 = A-group (warps 0..3), id 10 = B-group (warps 4..7)

    // cooperative weight copy
    {
        const ull* gsrc = reinterpret_cast<const ull*>(&d_stage);
        ull* sdst = reinterpret_cast<ull*>(&S->cw);
        const int N = (int)(sizeof(CW2) / 8);
        for (int i = tid; i < N; i += 256) sdst[i] = gsrc[i];
    }

    // prologue: stage t=0,1 inputs; zero state buffers sn[1], sy[1]
    {
        const int prow = tid >> 2, pch = tid & 3;
        const float4* gq = reinterpret_cast<const float4*>(
                               seq + (size_t)(rowbase + prow) * (T * F)) + pch;
        float4 v0 = gq[0], v1 = gq[4];
        S->sinb[0][4 * pch + 0][prow] = v0.x;
        S->sinb[0][4 * pch + 1][prow] = v0.y;
        S->sinb[0][4 * pch + 2][prow] = v0.z;
        S->sinb[0][4 * pch + 3][prow] = v0.w;
        S->sinb[1][4 * pch + 0][prow] = v1.x;
        S->sinb[1][4 * pch + 1][prow] = v1.y;
        S->sinb[1][4 * pch + 2][prow] = v1.z;
        S->sinb[1][4 * pch + 3][prow] = v1.w;
        ull* z1 = &S->sn[1][0][0];
        for (int i = tid; i < 12 * 64; i += 256) z1[i] = 0ull;
        ull* z2 = &S->sy[1][0][0];
        for (int i = tid; i < 24 * 64; i += 256) z2[i] = 0ull;
    }
    __syncthreads();

    // per-step input staging (A warps = tids 0..127): 8 floats each
    const int srow = tid >> 1, half = tid & 1;          // valid for tids 0..127
    const float4* gpA = reinterpret_cast<const float4*>(
                            seq + (size_t)(rowbase + (srow & 63)) * (T * F)) + half * 2;

    for (int t = 0; t < T; ++t) {
        const int cur = t & 1, oth = cur ^ 1;
        const int tn2 = (t + 2 < T) ? (t + 2) : (T - 1);
        float4 nv0, nv1;
        if (kh == 0) { nv0 = gpA[tn2 * 4]; nv1 = gpA[tn2 * 4 + 1]; }

        if (kh == 0) {
            // ===== A: x-part (W1rm + Wr1 pp0..1), ship, arrive =====
            ull a00 = S->cw.B1r[w][0], a01 = S->cw.B1r[w][1], a02 = S->cw.B1r[w][2];
            ull a10 = a00, a11 = a01, a12 = a02;
            #pragma unroll
            for (int kp = 0; kp < 8; ++kp) {
                const ulonglong2* q = reinterpret_cast<const ulonglong2*>(S->cw.W1rm[w][kp]);
                ulonglong2 q0 = q[0], q1 = q[1], q2 = q[2];
                float2 f0 = *reinterpret_cast<const float2*>(&S->sinb[cur][2 * kp][r0]);
                float2 f1 = *reinterpret_cast<const float2*>(&S->sinb[cur][2 * kp + 1][r0]);
                ull k00 = dup2(f0.x), k01 = dup2(f0.y);
                ull k10 = dup2(f1.x), k11 = dup2(f1.y);
                a00 = ffma2(k00, q0.x, a00); a01 = ffma2(k00, q0.y, a01); a02 = ffma2(k00, q1.x, a02);
                a00 = ffma2(k10, q1.y, a00); a01 = ffma2(k10, q2.x, a01); a02 = ffma2(k10, q2.y, a02);
                a10 = ffma2(k01, q0.x, a10); a11 = ffma2(k01, q0.y, a11); a12 = ffma2(k01, q1.x, a12);
                a10 = ffma2(k11, q1.y, a10); a11 = ffma2(k11, q2.x, a11); a12 = ffma2(k11, q2.y, a12);
            }
            #pragma unroll
            for (int pp = 0; pp < 2; ++pp) {
                const ulonglong2* q = reinterpret_cast<const ulonglong2*>(S->cw.Wr1m[w][pp]);
                ulonglong2 q0 = q[0], q1 = q[1], q2 = q[2];
                ulonglong2 X = *reinterpret_cast<const ulonglong2*>(&S->sn[oth][pp][r0]);
                float2 u0 = un2(X.x), u1 = un2(X.y);
                ull k0 = dup2(u0.x), k1 = dup2(u0.y);
                a00 = ffma2(k0, q0.x, a00); a01 = ffma2(k0, q0.y, a01); a02 = ffma2(k0, q1.x, a02);
                a00 = ffma2(k1, q1.y, a00); a01 = ffma2(k1, q2.x, a01); a02 = ffma2(k1, q2.y, a02);
                ull m0 = dup2(u1.x), m1 = dup2(u1.y);
                a10 = ffma2(m0, q0.x, a10); a11 = ffma2(m0, q0.y, a11); a12 = ffma2(m0, q1.x, a12);
                a10 = ffma2(m1, q1.y, a10); a11 = ffma2(m1, q2.x, a11); a12 = ffma2(m1, q2.y, a12);
            }
            *reinterpret_cast<ulonglong2*>(&S->pb1[w][0][r0]) = make_ulonglong2(a00, a10);
            *reinterpret_cast<ulonglong2*>(&S->pb1[w][1][r0]) = make_ulonglong2(a01, a11);
            *reinterpret_cast<ulonglong2*>(&S->pb1[w][2][r0]) = make_ulonglong2(a02, a12);
            barw_arrive(pidA);

            // ===== A: e over Wr2 pp0..21 (bias included), ship, arrive =====
            ull e00 = S->cw.B2n[w][0], e01 = S->cw.B2n[w][1], e02 = S->cw.B2n[w][2];
            ull e03 = S->cw.B2n[w][3], e04 = S->cw.B2n[w][4], e05 = S->cw.B2n[w][5];
            ull e10 = e00, e11 = e01, e12 = e02, e13 = e03, e14 = e04, e15 = e05;
            #pragma unroll
            for (int pp = 0; pp < 22; ++pp) {
                const ulonglong2* q = reinterpret_cast<const ulonglong2*>(S->cw.Wr2m[w][pp]);
                ulonglong2 q0 = q[0], q1 = q[1], q2 = q[2];
                ulonglong2 q3 = q[3], q4 = q[4], q5 = q[5];
                ulonglong2 Y = *reinterpret_cast<const ulonglong2*>(&S->sy[oth][pp][r0]);
                float2 u0 = un2(Y.x), u1 = un2(Y.y);
                ull k0 = dup2(u0.x), k1 = dup2(u0.y);
                e00 = ffma2(k0, q0.x, e00); e01 = ffma2(k0, q0.y, e01); e02 = ffma2(k0, q1.x, e02);
                e03 = ffma2(k0, q1.y, e03); e04 = ffma2(k0, q2.x, e04); e05 = ffma2(k0, q2.y, e05);
                e00 = ffma2(k1, q3.x, e00); e01 = ffma2(k1, q3.y, e01); e02 = ffma2(k1, q4.x, e02);
                e03 = ffma2(k1, q4.y, e03); e04 = ffma2(k1, q5.x, e04); e05 = ffma2(k1, q5.y, e05);
                ull m0 = dup2(u1.x), m1 = dup2(u1.y);
                e10 = ffma2(m0, q0.x, e10); e11 = ffma2(m0, q0.y, e11); e12 = ffma2(m0, q1.x, e12);
                e13 = ffma2(m0, q1.y, e13); e14 = ffma2(m0, q2.x, e14); e15 = ffma2(m0, q2.y, e15);
                e10 = ffma2(m1, q3.x, e10); e11 = ffma2(m1, q3.y, e11); e12 = ffma2(m1, q4.x, e12);
                e13 = ffma2(m1, q4.y, e13); e14 = ffma2(m1, q5.x, e14); e15 = ffma2(m1, q5.y, e15);
            }
            *reinterpret_cast<ulonglong2*>(&S->pbe[w][0][r0]) = make_ulonglong2(e00, e10);
            *reinterpret_cast<ulonglong2*>(&S->pbe[w][1][r0]) = make_ulonglong2(e01, e11);
            *reinterpret_cast<ulonglong2*>(&S->pbe[w][2][r0]) = make_ulonglong2(e02, e12);
            *reinterpret_cast<ulonglong2*>(&S->pbe[w][3][r0]) = make_ulonglong2(e03, e13);
            *reinterpret_cast<ulonglong2*>(&S->pbe[w][4][r0]) = make_ulonglong2(e04, e14);
            *reinterpret_cast<ulonglong2*>(&S->pbe[w][5][r0]) = make_ulonglong2(e05, e15);
            barw_arrive(pidE);

            // ===== A: group barrier (all A phase-1 sinb reads done), stage input =====
            barg_sync(9);
            S->sinb[cur][8 * half + 0][srow & 63] = nv0.x;
            S->sinb[cur][8 * half + 1][srow & 63] = nv0.y;
            S->sinb[cur][8 * half + 2][srow & 63] = nv0.z;
            S->sinb[cur][8 * half + 3][srow & 63] = nv0.w;
            S->sinb[cur][8 * half + 4][srow & 63] = nv1.x;
            S->sinb[cur][8 * half + 5][srow & 63] = nv1.y;
            S->sinb[cur][8 * half + 6][srow & 63] = nv1.z;
            S->sinb[cur][8 * half + 7][srow & 63] = nv1.w;
        } else {
            // ===== B: Wr1 pp2..11, combine A's x-partial, tanh, publish ns1 =====
            ull a00 = 0, a01 = 0, a02 = 0, a10 = 0, a11 = 0, a12 = 0;
            #pragma unroll
            for (int pp = 2; pp < 12; ++pp) {
                const ulonglong2* q = reinterpret_cast<const ulonglong2*>(S->cw.Wr1m[w][pp]);
                ulonglong2 q0 = q[0], q1 = q[1], q2 = q[2];
                ulonglong2 X = *reinterpret_cast<const ulonglong2*>(&S->sn[oth][pp][r0]);
                float2 u0 = un2(X.x), u1 = un2(X.y);
                ull k0 = dup2(u0.x), k1 = dup2(u0.y);
                a00 = ffma2(k0, q0.x, a00); a01 = ffma2(k0, q0.y, a01); a02 = ffma2(k0, q1.x, a02);
                a00 = ffma2(k1, q1.y, a00); a01 = ffma2(k1, q2.x, a01); a02 = ffma2(k1, q2.y, a02);
                ull m0 = dup2(u1.x), m1 = dup2(u1.y);
                a10 = ffma2(m0, q0.x, a10); a11 = ffma2(m0, q0.y, a11); a12 = ffma2(m0, q1.x, a12);
                a10 = ffma2(m1, q1.y, a10); a11 = ffma2(m1, q2.x, a11); a12 = ffma2(m1, q2.y, a12);
            }
            barw_sync(pidA);
            {
                ulonglong2 P0 = *reinterpret_cast<const ulonglong2*>(&S->pb1[w][0][r0]);
                ulonglong2 P1 = *reinterpret_cast<const ulonglong2*>(&S->pb1[w][1][r0]);
                ulonglong2 P2 = *reinterpret_cast<const ulonglong2*>(&S->pb1[w][2][r0]);
                a00 = fadd2(a00, P0.x); a10 = fadd2(a10, P0.y);
                a01 = fadd2(a01, P1.x); a11 = fadd2(a11, P1.y);
                a02 = fadd2(a02, P2.x); a12 = fadd2(a12, P2.y);
            }
            {
                float2 u0, u1;
                u0 = un2(a00); u1 = un2(a10);
                *reinterpret_cast<ulonglong2*>(&S->sn[cur][3 * w + 0][r0]) =
                    make_ulonglong2(pk2(tanh_f(u0.x), tanh_f(u0.y)), pk2(tanh_f(u1.x), tanh_f(u1.y)));
                u0 = un2(a01); u1 = un2(a11);
                *reinterpret_cast<ulonglong2*>(&S->sn[cur][3 * w + 1][r0]) =
                    make_ulonglong2(pk2(tanh_f(u0.x), tanh_f(u0.y)), pk2(tanh_f(u1.x), tanh_f(u1.y)));
                u0 = un2(a02); u1 = un2(a12);
                *reinterpret_cast<ulonglong2*>(&S->sn[cur][3 * w + 2][r0]) =
                    make_ulonglong2(pk2(tanh_f(u0.x), tanh_f(u0.y)), pk2(tanh_f(u1.x), tanh_f(u1.y)));
            }

            // ===== B: small e share (Wr2 pp22..23), zero bias =====
            ull e00 = 0, e01 = 0, e02 = 0, e03 = 0, e04 = 0, e05 = 0;
            ull e10 = 0, e11 = 0, e12 = 0, e13 = 0, e14 = 0, e15 = 0;
            #pragma unroll
            for (int pp = 22; pp < 24; ++pp) {
                const ulonglong2* q = reinterpret_cast<const ulonglong2*>(S->cw.Wr2m[w][pp]);
                ulonglong2 q0 = q[0], q1 = q[1], q2 = q[2];
                ulonglong2 q3 = q[3], q4 = q[4], q5 = q[5];
                ulonglong2 Y = *reinterpret_cast<const ulonglong2*>(&S->sy[oth][pp][r0]);
                float2 u0 = un2(Y.x), u1 = un2(Y.y);
                ull k0 = dup2(u0.x), k1 = dup2(u0.y);
                e00 = ffma2(k0, q0.x, e00); e01 = ffma2(k0, q0.y, e01); e02 = ffma2(k0, q1.x, e02);
                e03 = ffma2(k0, q1.y, e03); e04 = ffma2(k0, q2.x, e04); e05 = ffma2(k0, q2.y, e05);
                e00 = ffma2(k1, q3.x, e00); e01 = ffma2(k1, q3.y, e01); e02 = ffma2(k1, q4.x, e02);
                e03 = ffma2(k1, q4.y, e03); e04 = ffma2(k1, q5.x, e04); e05 = ffma2(k1, q5.y, e05);
                ull m0 = dup2(u1.x), m1 = dup2(u1.y);
                e10 = ffma2(m0, q0.x, e10); e11 = ffma2(m0, q0.y, e11); e12 = ffma2(m0, q1.x, e12);
                e13 = ffma2(m0, q1.y, e13); e14 = ffma2(m0, q2.x, e14); e15 = ffma2(m0, q2.y, e15);
                e10 = ffma2(m1, q3.x, e10); e11 = ffma2(m1, q3.y, e11); e12 = ffma2(m1, q4.x, e12);
                e13 = ffma2(m1, q4.y, e13); e14 = ffma2(m1, q5.x, e14); e15 = ffma2(m1, q5.y, e15);
            }

            barg_sync(10);   // B-group: all sn[cur] slices published

            // ===== B: Mm full GEMM + LN stats =====
            ull c00 = 0, c01 = 0, c02 = 0, c03 = 0, c04 = 0, c05 = 0;
            ull c10 = 0, c11 = 0, c12 = 0, c13 = 0, c14 = 0, c15 = 0;
            ull sm0 = 0, sm1 = 0, sq0 = 0, sq1 = 0;
            #pragma unroll
            for (int pp = 0; pp < 12; ++pp) {
                const ulonglong2* q = reinterpret_cast<const ulonglong2*>(S->cw.Mm[w][pp]);
                ulonglong2 q0 = q[0], q1 = q[1], q2 = q[2];
                ulonglong2 q3 = q[3], q4 = q[4], q5 = q[5];
                ulonglong2 X = *reinterpret_cast<const ulonglong2*>(&S->sn[cur][pp][r0]);
                sm0 = fadd2(sm0, X.x); sq0 = ffma2(X.x, X.x, sq0);
                sm1 = fadd2(sm1, X.y); sq1 = ffma2(X.y, X.y, sq1);
                float2 u0 = un2(X.x), u1 = un2(X.y);
                ull k0 = dup2(u0.x), k1 = dup2(u0.y);
                c00 = ffma2(k0, q0.x, c00); c01 = ffma2(k0, q0.y, c01); c02 = ffma2(k0, q1.x, c02);
                c03 = ffma2(k0, q1.y, c03); c04 = ffma2(k0, q2.x, c04); c05 = ffma2(k0, q2.y, c05);
                c00 = ffma2(k1, q3.x, c00); c01 = ffma2(k1, q3.y, c01); c02 = ffma2(k1, q4.x, c02);
                c03 = ffma2(k1, q4.y, c03); c04 = ffma2(k1, q5.x, c04); c05 = ffma2(k1, q5.y, c05);
                ull m0 = dup2(u1.x), m1 = dup2(u1.y);
                c10 = ffma2(m0, q0.x, c10); c11 = ffma2(m0, q0.y, c11); c12 = ffma2(m0, q1.x, c12);
                c13 = ffma2(m0, q1.y, c13); c14 = ffma2(m0, q2.x, c14); c15 = ffma2(m0, q2.y, c15);
                c10 = ffma2(m1, q3.x, c10); c11 = ffma2(m1, q3.y, c11); c12 = ffma2(m1, q4.x, c12);
                c13 = ffma2(m1, q4.y, c13); c14 = ffma2(m1, q5.x, c14); c15 = ffma2(m1, q5.y, c15);
            }

            barw_sync(pidE);  // A's e-partials ready
            {
                ulonglong2 P;
                P = *reinterpret_cast<const ulonglong2*>(&S->pbe[w][0][r0]); e00 = fadd2(e00, P.x); e10 = fadd2(e10, P.y);
                P = *reinterpret_cast<const ulonglong2*>(&S->pbe[w][1][r0]); e01 = fadd2(e01, P.x); e11 = fadd2(e11, P.y);
                P = *reinterpret_cast<const ulonglong2*>(&S->pbe[w][2][r0]); e02 = fadd2(e02, P.x); e12 = fadd2(e12, P.y);
                P = *reinterpret_cast<const ulonglong2*>(&S->pbe[w][3][r0]); e03 = fadd2(e03, P.x); e13 = fadd2(e13, P.y);
                P = *reinterpret_cast<const ulonglong2*>(&S->pbe[w][4][r0]); e04 = fadd2(e04, P.x); e14 = fadd2(e14, P.y);
                P = *reinterpret_cast<const ulonglong2*>(&S->pbe[w][5][r0]); e05 = fadd2(e05, P.x); e15 = fadd2(e15, P.y);
            }
            {
                float2 us = un2(sm0), uq = un2(sq0);
                float mu   = (us.x + us.y) * (1.0f / 24.0f);
                float var  = fmaf(-mu, mu, (uq.x + uq.y) * (1.0f / 24.0f));
                float rstd = rsqrtf(var + LN_EPS);
                ull mun = dup2(-mu), rsd = dup2(rstd);
                c00 = ffma2(rsd, ffma2(mun, S->cw.Cmp[w][0], c00), e00);
                c01 = ffma2(rsd, ffma2(mun, S->cw.Cmp[w][1], c01), e01);
                c02 = ffma2(rsd, ffma2(mun, S->cw.Cmp[w][2], c02), e02);
                c03 = ffma2(rsd, ffma2(mun, S->cw.Cmp[w][3], c03), e03);
                c04 = ffma2(rsd, ffma2(mun, S->cw.Cmp[w][4], c04), e04);
                c05 = ffma2(rsd, ffma2(mun, S->cw.Cmp[w][5], c05), e05);
                float2 vs = un2(sm1), vq = un2(sq1);
                float mu1   = (vs.x + vs.y) * (1.0f / 24.0f);
                float var1  = fmaf(-mu1, mu1, (vq.x + vq.y) * (1.0f / 24.0f));
                float rstd1 = rsqrtf(var1 + LN_EPS);
                ull mun1 = dup2(-mu1), rsd1 = dup2(rstd1);
                c10 = ffma2(rsd1, ffma2(mun1, S->cw.Cmp[w][0], c10), e10);
                c11 = ffma2(rsd1, ffma2(mun1, S->cw.Cmp[w][1], c11), e11);
                c12 = ffma2(rsd1, ffma2(mun1, S->cw.Cmp[w][2], c12), e12);
                c13 = ffma2(rsd1, ffma2(mun1, S->cw.Cmp[w][3], c13), e13);
                c14 = ffma2(rsd1, ffma2(mun1, S->cw.Cmp[w][4], c14), e14);
                c15 = ffma2(rsd1, ffma2(mun1, S->cw.Cmp[w][5], c15), e15);
            }
            {
                float2 u0, u1;
                u0 = un2(c00); u1 = un2(c10);
                *reinterpret_cast<ulonglong2*>(&S->sy[cur][6 * w + 0][r0]) =
                    make_ulonglong2(pk2(tanh_f(u0.x), tanh_f(u0.y)), pk2(tanh_f(u1.x), tanh_f(u1.y)));
                u0 = un2(c01); u1 = un2(c11);
                *reinterpret_cast<ulonglong2*>(&S->sy[cur][6 * w + 1][r0]) =
                    make_ulonglong2(pk2(tanh_f(u0.x), tanh_f(u0.y)), pk2(tanh_f(u1.x), tanh_f(u1.y)));
                u0 = un2(c02); u1 = un2(c12);
                *reinterpret_cast<ulonglong2*>(&S->sy[cur][6 * w + 2][r0]) =
                    make_ulonglong2(pk2(tanh_f(u0.x), tanh_f(u0.y)), pk2(tanh_f(u1.x), tanh_f(u1.y)));
                u0 = un2(c03); u1 = un2(c13);
                *reinterpret_cast<ulonglong2*>(&S->sy[cur][6 * w + 3][r0]) =
                    make_ulonglong2(pk2(tanh_f(u0.x), tanh_f(u0.y)), pk2(tanh_f(u1.x), tanh_f(u1.y)));
                u0 = un2(c04); u1 = un2(c14);
                *reinterpret_cast<ulonglong2*>(&S->sy[cur][6 * w + 4][r0]) =
                    make_ulonglong2(pk2(tanh_f(u0.x), tanh_f(u0.y)), pk2(tanh_f(u1.x), tanh_f(u1.y)));
                u0 = un2(c05); u1 = un2(c15);
                *reinterpret_cast<ulonglong2*>(&S->sy[cur][6 * w + 5][r0]) =
                    make_ulonglong2(pk2(tanh_f(u0.x), tanh_f(u0.y)), pk2(tanh_f(u1.x), tanh_f(u1.y)));
            }
        }
        __syncthreads();   // end-of-step: sy[cur], sn[cur], staged input visible; pb WARs cleared
    }

    // ---- epilogue: sigmoid(LN(ns2; g2,be2) @ Wout + bout) by warp 0 ----
    if (warp == 0) {
        ull zp0[24], zp1[24];
        #pragma unroll
        for (int pp = 0; pp < 24; ++pp) {
            ulonglong2 X = *reinterpret_cast<const ulonglong2*>(&S->sy[1][pp][r0]);
            zp0[pp] = X.x; zp1[pp] = X.y;
        }
        float res[2];
        #pragma unroll
        for (int rr = 0; rr < 2; ++rr) {
            const ull* zp = rr ? zp1 : zp0;
            ull sm2 = zp[0], sq2 = fmul2(zp[0], zp[0]);
            #pragma unroll
            for (int pp = 1; pp < 24; ++pp) {
                sm2 = fadd2(sm2, zp[pp]);
                sq2 = ffma2(zp[pp], zp[pp], sq2);
            }
            float2 us = un2(sm2), uq = un2(sq2);
            float mu   = (us.x + us.y) * (1.0f / 48.0f);
            float var  = fmaf(-mu, mu, (uq.x + uq.y) * (1.0f / 48.0f));
            float rstd = rsqrtf(var + LN_EPS);
            ull mun = dup2(-mu), rsd = dup2(rstd);
            ull acc = 0;
            #pragma unroll
            for (int pp = 0; pp < 24; ++pp) {
                ull h = fmul2(fadd2(zp[pp], mun), rsd);
                h = ffma2(h, S->cw.G2f[pp], S->cw.Be2f[pp]);
                acc = ffma2(h, S->cw.Wof[pp], acc);
            }
            float2 ua = un2(acc);
            float z = ua.x + ua.y + S->cw.bout;
            res[rr] = __fdividef(1.0f, 1.0f + __expf(-z));
        }
        *reinterpret_cast<float2*>(&out[rowbase + r0]) = make_float2(res[0], res[1]);
    }
}

extern "C" void kernel_launch(void* const* d_in, const int* in_sizes, int n_in,
                              void* d_out, int out_size)
{
    const float* seq  = (const float*)d_in[0];
    const float* W1   = (const float*)d_in[1];
    const float* b1   = (const float*)d_in[2];
    const float* Wr1  = (const float*)d_in[3];
    const float* br1  = (const float*)d_in[4];
    const float* g1   = (const float*)d_in[5];
    const float* be1  = (const float*)d_in[6];
    const float* W2   = (const float*)d_in[7];
    const float* b2   = (const float*)d_in[8];
    const float* Wr2  = (const float*)d_in[9];
    const float* br2  = (const float*)d_in[10];
    const float* g2   = (const float*)d_in[11];
    const float* be2  = (const float*)d_in[12];
    const float* Wout = (const float*)d_in[13];
    const float* bout = (const float*)d_in[14];

    prep_kernel<<<1, 256>>>(W1, b1, Wr1, br1, g1, be1,
                            W2, b2, Wr2, br2, g2, be2, Wout, bout);

    static int smem_configured = 0;
    if (!smem_configured) {
        cudaFuncSetAttribute(rnn_main, cudaFuncAttributeMaxDynamicSharedMemorySize,
                             (int)sizeof(Smem5));
        smem_configured = 1;
    }

    const int B = in_sizes[0] / (T * F);     // 8192
    rnn_main<<<B / 64, 256, sizeof(Smem5)>>>(seq, (float*)d_out);
}